// round 4
// baseline (speedup 1.0000x reference)
#include <cuda_runtime.h>

// BillehColumn GLIF3 simulation, forward only.
// Round 4: 2 threads per neuron (each owns 2 of the 4 receptors) to double
// warp occupancy of the latency-bound step kernel. Pair cooperates via warp
// shuffles; spike scatter is split across the pair.

#define Nn 100000
#define Rr 4
#define Ee 2000000
#define Tt 50
#define NRr (Nn * Rr)
#define SS 64                 // synapse slots per pre-neuron
#define OVF_CAP 4096

// Contiguous zero-initialized state blob (floats):
//   [0,        800000)  rec[2][NR]
//   [800000,  1200000)  psc[NR]
//   [1200000, 1600000)  psc_rise[NR]
//   [1600000, 1800000)  asc[2N]
//   [1800000, 1900000)  cnt[N]      (as int)
//   [1900000, 1900004)  ovf_cnt + pad (as int)
#define BLOB_FLOATS 1900004
#define OFF_REC 0
#define OFF_PSC 800000
#define OFF_PR  1200000
#define OFF_ASC 1600000
#define OFF_CNT 1800000
#define OFF_OVF 1900000

__device__ float  g_blob[BLOB_FLOATS];
__device__ float4 g_pA[Nn];        // vth, (vreset - vth), tref, decay
__device__ float4 g_pB[Nn];        // cf, el, amp0, amp1
__device__ float2 g_pC[Nn];        // ascd0, ascd1
__device__ float4 g_state[Nn];     // v, r, z, unused
__device__ int    g_syn_tgt[Nn * SS];
__device__ float  g_syn_w[Nn * SS];
__device__ int    g_ovf_pre[OVF_CAP];
__device__ int    g_ovf_tgt[OVF_CAP];
__device__ float  g_ovf_w[OVF_CAP];

// ---------------------------------------------------------------------------
// Fused init: zero the blob (float4 grid-stride), pack params, init state.
__global__ void k_prep(const float* __restrict__ v0,
                       const float* __restrict__ vth,
                       const float* __restrict__ vreset,
                       const float* __restrict__ tref,
                       const float* __restrict__ decay,
                       const float* __restrict__ cf,
                       const float* __restrict__ el,
                       const float* __restrict__ amps,
                       const float* __restrict__ ascd) {
    int i = blockIdx.x * blockDim.x + threadIdx.x;
    const int nf4 = BLOB_FLOATS / 4;
    float4* blob4 = (float4*)g_blob;
    for (int j = i; j < nf4; j += gridDim.x * blockDim.x) {
        blob4[j] = make_float4(0.f, 0.f, 0.f, 0.f);
    }
    if (i < Nn) {
        float t = vth[i];
        g_pA[i] = make_float4(t, vreset[i] - t, tref[i], decay[i]);
        float2 am = *(const float2*)(&amps[2 * i]);
        g_pB[i] = make_float4(cf[i], el[i], am.x, am.y);
        g_pC[i] = *(const float2*)(&ascd[2 * i]);
        g_state[i] = make_float4(v0[i], 0.f, 0.f, 0.f);
    }
}

// ---------------------------------------------------------------------------
// Single-pass synapse bucketing: slot = pre*SS + running count.
// 4 synapses per thread (int4/float4 loads).
__global__ void k_fill(const int* __restrict__ pre,
                       const int* __restrict__ post,
                       const int* __restrict__ rcp,
                       const float* __restrict__ w) {
    int i = blockIdx.x * blockDim.x + threadIdx.x;   // quad index
    if (i >= Ee / 4) return;
    int4 p4 = ((const int4*)pre)[i];
    int4 q4 = ((const int4*)post)[i];
    int4 r4 = ((const int4*)rcp)[i];
    float4 w4 = ((const float4*)w)[i];

    int* cnt = (int*)(g_blob + OFF_CNT);
    int* ovf_cnt = (int*)(g_blob + OFF_OVF);

    int   ps[4] = {p4.x, p4.y, p4.z, p4.w};
    int   ts[4] = {q4.x * Rr + r4.x, q4.y * Rr + r4.y,
                   q4.z * Rr + r4.z, q4.w * Rr + r4.w};
    float ws[4] = {w4.x, w4.y, w4.z, w4.w};

#pragma unroll
    for (int k = 0; k < 4; k++) {
        int p = ps[k];
        int c = atomicAdd(&cnt[p], 1);
        if (c < SS) {
            g_syn_tgt[p * SS + c] = ts[k];
            g_syn_w[p * SS + c] = ws[k];
        } else {
            int o = atomicAdd(ovf_cnt, 1);
            if (o < OVF_CAP) {
                g_ovf_pre[o] = p;
                g_ovf_tgt[o] = ts[k];
                g_ovf_w[o] = ws[k];
            }
        }
    }
}

// ---------------------------------------------------------------------------
// One timestep, 2 threads per neuron. gid = 2*n + h; each half owns
// receptors {2h, 2h+1}. float2 index into rec/x/psc/pr arrays == gid.
__global__ void k_step(const float* __restrict__ x_t,
                       float* __restrict__ out,
                       const float* __restrict__ syn_decay,
                       const float* __restrict__ psc_init,
                       int parity) {
    const int gid = blockIdx.x * blockDim.x + threadIdx.x;
    const int n = gid >> 1;
    const int h = gid & 1;
    const bool act = (n < Nn);

    const float2 sd = ((const float2*)syn_decay)[h];
    const float2 pi = ((const float2*)psc_init)[h];

    float* rec_cur = g_blob + OFF_REC + parity * NRr;
    float* rec_nxt = g_blob + OFF_REC + (parity ^ 1) * NRr;
    float* pscp = g_blob + OFF_PSC;
    float* prp  = g_blob + OFF_PR;
    float2* ascp = (float2*)(g_blob + OFF_ASC);

    float partial = 0.f;
    if (act) {
        float2 rec = __ldcg((const float2*)rec_cur + gid);
        __stcg((float2*)rec_cur + gid, make_float2(0.f, 0.f));

        float2 x   = __ldg((const float2*)x_t + gid);
        float2 psc = *((float2*)pscp + gid);
        float2 pr  = *((float2*)prp + gid);

        float in0 = rec.x + x.x;
        float in1 = rec.y + x.y;

        float2 npr, npsc;
        npr.x = pr.x * sd.x + in0 * pi.x;
        npr.y = pr.y * sd.y + in1 * pi.y;
        npsc.x = psc.x * sd.x + sd.x * pr.x;
        npsc.y = psc.y * sd.y + sd.y * pr.y;

        *((float2*)pscp + gid) = npsc;
        *((float2*)prp + gid) = npr;

        partial = npsc.x + npsc.y;
    }

    // Combine receptor partial sums within the pair (lanes 2k, 2k+1).
    float psum = partial + __shfl_xor_sync(0xffffffffu, partial, 1);

    // Even half does the scalar neuron update.
    float zn = 0.f;
    if (act && h == 0) {
        float4 st = g_state[n];        // v, r, z
        float2 a  = ascp[n];
        float4 pA = g_pA[n];           // vth, rst, tref, decay
        float4 pB = g_pB[n];           // cf, el, amp0, amp1
        float2 pC = g_pC[n];           // ascd

        float z = st.z;
        float input_current = psum + (a.x + a.y);   // OLD asc

        a.x = pC.x * a.x + z * pB.z;
        a.y = pC.y * a.y + z * pB.w;
        ascp[n] = a;

        float nv = pA.w * st.x + pB.x * (input_current + pB.y) + z * pA.y;
        float vsc = (nv - pA.x) / pA.x;

        zn = (vsc > 0.f) ? 1.f : 0.f;
        if (st.y > 0.f) zn = 0.f;
        float rn = fmaxf(st.y - 1.f + zn * pA.z, 0.f);

        g_state[n] = make_float4(nv, rn, zn, 0.f);
        out[n] = zn;
    }

    // Broadcast spike decision to the odd half.
    zn = __shfl_sync(0xffffffffu, zn, threadIdx.x & ~1);

    if (act && zn != 0.f) {
        int* cnt = (int*)(g_blob + OFF_CNT);
        int c = cnt[n];
        int m = (c < SS) ? c : SS;
        int base = n * SS;
        // Pair splits the scatter: h, h+2, h+4, ...
        for (int s = h; s < m; s += 2) {
            atomicAdd(&rec_nxt[g_syn_tgt[base + s]], g_syn_w[base + s]);
        }
        if (h == 0 && c > SS) {  // overflow (practically never)
            int oc = *(int*)(g_blob + OFF_OVF);
            if (oc > OVF_CAP) oc = OVF_CAP;
            for (int o = 0; o < oc; o++) {
                if (g_ovf_pre[o] == n) {
                    atomicAdd(&rec_nxt[g_ovf_tgt[o]], g_ovf_w[o]);
                }
            }
        }
    }
}

// ---------------------------------------------------------------------------
extern "C" void kernel_launch(void* const* d_in, const int* in_sizes, int n_in,
                              void* d_out, int out_size) {
    const float* w_rec     = (const float*)d_in[0];
    const float* x_ext     = (const float*)d_in[1];
    const float* v0        = (const float*)d_in[2];
    const float* vth       = (const float*)d_in[3];
    const float* vreset    = (const float*)d_in[4];
    const float* tref      = (const float*)d_in[5];
    const float* decay     = (const float*)d_in[6];
    const float* cf        = (const float*)d_in[7];
    const float* el        = (const float*)d_in[8];
    const float* amps      = (const float*)d_in[9];
    const float* ascd      = (const float*)d_in[10];
    const float* syn_decay = (const float*)d_in[11];
    const float* psc_init  = (const float*)d_in[12];
    const int*   pre       = (const int*)d_in[13];
    const int*   post      = (const int*)d_in[14];
    const int*   rcp       = (const int*)d_in[15];
    float* out = (float*)d_out;

    k_prep<<<1856, 256>>>(v0, vth, vreset, tref, decay, cf, el, amps, ascd);
    k_fill<<<(Ee / 4 + 255) / 256, 256>>>(pre, post, rcp, w_rec);

    for (int t = 0; t < Tt; t++) {
        k_step<<<(2 * Nn + 255) / 256, 256>>>(
            x_ext + (size_t)t * NRr,
            out + (size_t)t * Nn,
            syn_decay, psc_init, t & 1);
    }
}